// round 13
// baseline (speedup 1.0000x reference)
#include <cuda_runtime.h>
#include <cuda_fp16.h>
#include <cstdint>

// ---------------- problem constants ----------------
#define SCALE 0.1767766952966369f   // 32^-0.5

// ---------------- smem layout (bytes) ----------------
#define STRC 144                     // A-tile channel-major row stride (bytes): 64 tok *2 + 16
#define SAW  18464                   // per-window A region (128*144 = 18432, +32 bank rotate)
#define STRA 136                     // token-major fp16 row stride in halves (272 B) for K/V/A'
#define SK   73856                   // K fp16 tile [64][136]
#define SV   91264                   // V fp16 tile
#define SPO  73856                   // proj-out fp32 [64][132] overlays K+V
#define STRQ 132
#define SMEM_BYTES 108672

#define NWIN_PER_CTA 4
#define GRID 2048

// ---------------- ptx helpers ----------------
__device__ __forceinline__ uint32_t smem_u32(const void* p) {
    uint32_t a;
    asm("{ .reg .u64 t; cvta.to.shared.u64 t, %1; cvt.u32.u64 %0, t; }" : "=r"(a) : "l"(p));
    return a;
}
__device__ __forceinline__ void ldsm4(uint32_t* r, uint32_t addr) {
    asm volatile("ldmatrix.sync.aligned.m8n8.x4.shared.b16 {%0,%1,%2,%3}, [%4];"
                 : "=r"(r[0]), "=r"(r[1]), "=r"(r[2]), "=r"(r[3]) : "r"(addr));
}
__device__ __forceinline__ void ldsm4t(uint32_t* r, uint32_t addr) {
    asm volatile("ldmatrix.sync.aligned.m8n8.x4.trans.shared.b16 {%0,%1,%2,%3}, [%4];"
                 : "=r"(r[0]), "=r"(r[1]), "=r"(r[2]), "=r"(r[3]) : "r"(addr));
}
__device__ __forceinline__ void mma16816(float* c, const uint32_t* a,
                                         uint32_t b0, uint32_t b1) {
    asm volatile(
        "mma.sync.aligned.m16n8k16.row.col.f32.f16.f16.f32 "
        "{%0,%1,%2,%3}, {%4,%5,%6,%7}, {%8,%9}, {%0,%1,%2,%3};"
        : "+f"(c[0]), "+f"(c[1]), "+f"(c[2]), "+f"(c[3])
        : "r"(a[0]), "r"(a[1]), "r"(a[2]), "r"(a[3]), "r"(b0), "r"(b1));
}
__device__ __forceinline__ uint32_t pkh2(float x, float y) {
    __half2 H = __halves2half2(__float2half_rn(x), __float2half_rn(y));
    return *(uint32_t*)&H;
}

// ---------------- weight B-fragments in canonical m16n8k16 lane layout ----------
__device__ uint4 g_wfragQKV[3 * 4 * 8 * 2 * 32];   // 96 KB
__device__ uint4 g_wfragP[4 * 8 * 2 * 32];         // 32 KB

__global__ void init_weights_kernel(const float* __restrict__ wqkv,
                                    const float* __restrict__ wproj) {
    int t = blockIdx.x * blockDim.x + threadIdx.x;   // 8192 threads
    bool isP = t >= 6144;
    int e = isP ? t - 6144 : t;
    int lane = e & 31, g = (e >> 5) & 1, kk = (e >> 6) & 7, nbi = (e >> 9) & 3;
    int c = isP ? 0 : (e >> 11);
    int gid = lane >> 2, tig = lane & 3;
    int n_a = nbi * 32 + g * 16 + gid;
    int n_b = n_a + 8;
    int k0 = kk * 16 + 2 * tig;
    float w00, w01, w10, w11, w20, w21, w30, w31;
    if (isP) {
        w00 = wproj[k0 * 128 + n_a];       w01 = wproj[(k0 + 1) * 128 + n_a];
        w10 = wproj[(k0 + 8) * 128 + n_a]; w11 = wproj[(k0 + 9) * 128 + n_a];
        w20 = wproj[k0 * 128 + n_b];       w21 = wproj[(k0 + 1) * 128 + n_b];
        w30 = wproj[(k0 + 8) * 128 + n_b]; w31 = wproj[(k0 + 9) * 128 + n_b];
    } else {
        int nb0 = c * 128;
        w00 = wqkv[k0 * 384 + nb0 + n_a];       w01 = wqkv[(k0 + 1) * 384 + nb0 + n_a];
        w10 = wqkv[(k0 + 8) * 384 + nb0 + n_a]; w11 = wqkv[(k0 + 9) * 384 + nb0 + n_a];
        w20 = wqkv[k0 * 384 + nb0 + n_b];       w21 = wqkv[(k0 + 1) * 384 + nb0 + n_b];
        w30 = wqkv[(k0 + 8) * 384 + nb0 + n_b]; w31 = wqkv[(k0 + 9) * 384 + nb0 + n_b];
    }
    uint4 v;
    v.x = pkh2(w00, w01); v.y = pkh2(w10, w11);
    v.z = pkh2(w20, w21); v.w = pkh2(w30, w31);
    (isP ? g_wfragP : g_wfragQKV)[e] = v;
}

// ---------------- main kernel: 256 threads, 2 CTAs/SM, 4 fused windows/CTA ----
__global__ __launch_bounds__(256, 2)
void swin_mma_kernel(const float* __restrict__ x,
                     const float* __restrict__ bproj,
                     float* __restrict__ out) {
    extern __shared__ char smem[];
    const uint32_t sb = smem_u32(smem);
    const int tid  = threadIdx.x;
    const int wid  = tid >> 5;
    const int lane = tid & 31;

    const int bid  = blockIdx.x;
    const int win0 = bid * NWIN_PER_CTA;
    const int b0   = win0 >> 10;
    const int wh0  = (win0 >> 5) & 31;
    const int ww0  = win0 & 31;

    // scatter mapping: 64 tokens x 4 channel-blocks of 32 contiguous ch
    const int l8   = tid & 63;
    const int rrS  = l8 >> 3, cc8S = l8 & 7;
    const int ch0  = (tid >> 6) * 32;          // 0,32,64,96

    // warp roles: 2 (M) x 4 (N); warp tile 32 rows x 32 cols
    const int m0  = (wid >> 2) * 32;
    const int nbi = wid & 3;
    const int nb  = nbi * 32;
    const int gid = lane >> 2, tig = lane & 3;

    // trans-A per-lane offsets (channel-major A tiles)
    const uint32_t kLane = (uint32_t)(((lane & 7) + ((lane >> 4) & 1) * 8) * STRC);
    uint32_t aT[2], aOffP[2];
    #pragma unroll
    for (int mt = 0; mt < 2; ++mt) {
        aT[mt] = kLane + (uint32_t)((m0 + mt * 16 + ((lane >> 3) & 1) * 8) * 2);
        aOffP[mt] = (uint32_t)((m0 + mt * 16 + ((lane >> 3) & 1) * 8 + (lane & 7)) * 272 +
                               (lane >> 4) * 16);
    }
    const uint32_t bRowOff = (uint32_t)((((lane >> 4) & 1) * 8 + (lane & 7)) * 272);
    const uint32_t bKOff   = (uint32_t)(((lane >> 3) & 1) * 16);

    // ---- Prologue: fused 4-window gather, fp32 -> fp16, channel-major A tiles
    {
        const int s0   = ww0 * 8 + 4;
        const int sub  = lane >> 3, li = lane & 7;
        const int wiA  = li >> 1, cc8g = (li & 1) * 4;
        const int gwb  = (s0 + li * 4) & 255;
        const float* xb = x + (size_t)b0 * (128u * 65536u);
        #pragma unroll 4
        for (int it = 0; it < 32; ++it) {
            int pairIdx = wid * 128 + it * 4 + sub;
            int ch = pairIdx >> 3, rr = pairIdx & 7;
            int gh = (wh0 * 8 + rr + 4) & 255;
            float4 v = __ldg((const float4*)(xb + (size_t)ch * 65536u + gh * 256 + gwb));
            int token = rr * 8 + cc8g;
            uint2 hv;
            hv.x = pkh2(v.x, v.y);
            hv.y = pkh2(v.z, v.w);
            *(uint2*)(smem + wiA * SAW + ch * STRC + token * 2) = hv;
        }
    }
    __syncthreads();

    for (int i = 0; i < NWIN_PER_CTA; ++i) {
        const uint32_t saI = (uint32_t)(i * SAW);
        const int ww = ww0 + i;
        const int ghS = (wh0 * 8 + rrS + 4) & 255;
        const int gwS = (ww * 8 + cc8S + 4) & 255;
        const size_t gbase = (size_t)b0 * (128u * 65536u) + (size_t)ghS * 256 + (size_t)gwS;

        // ---- Phase 2a: Q+K GEMM (trans-A from channel-major tile) ----
        uint32_t qf[2][2][4];
        {
            float accA[2][2][4][4];
            #pragma unroll
            for (int c = 0; c < 2; ++c)
                #pragma unroll
                for (int mt = 0; mt < 2; ++mt)
                    #pragma unroll
                    for (int j = 0; j < 4; ++j)
                        #pragma unroll
                        for (int q = 0; q < 4; ++q) accA[c][mt][j][q] = 0.f;

            #pragma unroll
            for (int kk = 0; kk < 8; ++kk) {
                uint32_t ah[2][4];
                ldsm4t(ah[0], sb + saI + aT[0] + kk * (16 * STRC));
                ldsm4t(ah[1], sb + saI + aT[1] + kk * (16 * STRC));
                #pragma unroll
                for (int c = 0; c < 2; ++c) {
                    const int base = (((c * 4 + nbi) * 8 + kk) * 2) * 32 + lane;
                    uint4 w0 = __ldg(&g_wfragQKV[base]);
                    uint4 w1 = __ldg(&g_wfragQKV[base + 32]);
                    uint32_t bb[2][4] = {{w0.x, w0.y, w0.z, w0.w},
                                         {w1.x, w1.y, w1.z, w1.w}};
                    #pragma unroll
                    for (int mt = 0; mt < 2; ++mt)
                        #pragma unroll
                        for (int j = 0; j < 4; ++j) {
                            const int g = j >> 1, e = (j & 1) * 2;
                            mma16816(accA[c][mt][j], ah[mt], bb[g][e], bb[g][e + 1]);
                        }
                }
            }

            #pragma unroll
            for (int mt = 0; mt < 2; ++mt)
                #pragma unroll
                for (int kk2 = 0; kk2 < 2; ++kk2) {
                    qf[mt][kk2][0] = pkh2(accA[0][mt][2 * kk2][0],     accA[0][mt][2 * kk2][1]);
                    qf[mt][kk2][1] = pkh2(accA[0][mt][2 * kk2][2],     accA[0][mt][2 * kk2][3]);
                    qf[mt][kk2][2] = pkh2(accA[0][mt][2 * kk2 + 1][0], accA[0][mt][2 * kk2 + 1][1]);
                    qf[mt][kk2][3] = pkh2(accA[0][mt][2 * kk2 + 1][2], accA[0][mt][2 * kk2 + 1][3]);
                }

            __half* T = (__half*)(smem + SK);
            #pragma unroll
            for (int mt = 0; mt < 2; ++mt)
                #pragma unroll
                for (int j = 0; j < 4; ++j) {
                    int ccol = nb + j * 8 + 2 * tig;
                    *(uint32_t*)&T[(m0 + mt * 16 + gid) * STRA + ccol] =
                        pkh2(accA[1][mt][j][0], accA[1][mt][j][1]);
                    *(uint32_t*)&T[(m0 + mt * 16 + gid + 8) * STRA + ccol] =
                        pkh2(accA[1][mt][j][2], accA[1][mt][j][3]);
                }
        }

        // ---- Phase 2b: V GEMM ----
        {
            float accV[2][4][4];
            #pragma unroll
            for (int mt = 0; mt < 2; ++mt)
                #pragma unroll
                for (int j = 0; j < 4; ++j)
                    #pragma unroll
                    for (int q = 0; q < 4; ++q) accV[mt][j][q] = 0.f;

            #pragma unroll
            for (int kk = 0; kk < 8; ++kk) {
                uint32_t ah[2][4];
                ldsm4t(ah[0], sb + saI + aT[0] + kk * (16 * STRC));
                ldsm4t(ah[1], sb + saI + aT[1] + kk * (16 * STRC));
                const int base = (((2 * 4 + nbi) * 8 + kk) * 2) * 32 + lane;
                uint4 w0 = __ldg(&g_wfragQKV[base]);
                uint4 w1 = __ldg(&g_wfragQKV[base + 32]);
                uint32_t bb[2][4] = {{w0.x, w0.y, w0.z, w0.w}, {w1.x, w1.y, w1.z, w1.w}};
                #pragma unroll
                for (int mt = 0; mt < 2; ++mt)
                    #pragma unroll
                    for (int j = 0; j < 4; ++j) {
                        const int g = j >> 1, e = (j & 1) * 2;
                        mma16816(accV[mt][j], ah[mt], bb[g][e], bb[g][e + 1]);
                    }
            }
            __half* T = (__half*)(smem + SV);
            #pragma unroll
            for (int mt = 0; mt < 2; ++mt)
                #pragma unroll
                for (int j = 0; j < 4; ++j) {
                    int ccol = nb + j * 8 + 2 * tig;
                    *(uint32_t*)&T[(m0 + mt * 16 + gid) * STRA + ccol] =
                        pkh2(accV[mt][j][0], accV[mt][j][1]);
                    *(uint32_t*)&T[(m0 + mt * 16 + gid + 8) * STRA + ccol] =
                        pkh2(accV[mt][j][2], accV[mt][j][3]);
                }
        }
        __syncthreads();

        // ---- Phase 3: attention (1-pass fp16), A' token-major overlays A_i ----
        {
            const int head = nbi;

            float sacc[2][8][4];
            #pragma unroll
            for (int mt = 0; mt < 2; ++mt)
                #pragma unroll
                for (int j = 0; j < 8; ++j)
                    #pragma unroll
                    for (int q = 0; q < 4; ++q) sacc[mt][j][q] = 0.f;

            #pragma unroll
            for (int kk2 = 0; kk2 < 2; ++kk2) {
                const uint32_t ka = kk2 * 32;
                uint32_t kh[4][4];
                #pragma unroll
                for (int g = 0; g < 4; ++g) {
                    uint32_t ro = (uint32_t)(g * 16 * 272) + bRowOff + bKOff +
                                  (uint32_t)(head * 64) + ka;
                    ldsm4(kh[g], sb + SK + ro);
                }
                #pragma unroll
                for (int mt = 0; mt < 2; ++mt)
                    #pragma unroll
                    for (int j = 0; j < 8; ++j) {
                        const int g = j >> 1, e = (j & 1) * 2;
                        mma16816(sacc[mt][j], qf[mt][kk2], kh[g][e], kh[g][e + 1]);
                    }
            }

            const unsigned FULL = 0xffffffffu;
            float inv0[2], inv1[2];
            #pragma unroll
            for (int mt = 0; mt < 2; ++mt) {
                float mx0 = -1e30f, mx1 = -1e30f;
                #pragma unroll
                for (int j = 0; j < 8; ++j) {
                    mx0 = fmaxf(mx0, fmaxf(sacc[mt][j][0], sacc[mt][j][1]));
                    mx1 = fmaxf(mx1, fmaxf(sacc[mt][j][2], sacc[mt][j][3]));
                }
                mx0 = fmaxf(mx0, __shfl_xor_sync(FULL, mx0, 1));
                mx0 = fmaxf(mx0, __shfl_xor_sync(FULL, mx0, 2));
                mx1 = fmaxf(mx1, __shfl_xor_sync(FULL, mx1, 1));
                mx1 = fmaxf(mx1, __shfl_xor_sync(FULL, mx1, 2));
                float sum0 = 0.f, sum1 = 0.f;
                #pragma unroll
                for (int j = 0; j < 8; ++j) {
                    float e0 = __expf((sacc[mt][j][0] - mx0) * SCALE);
                    float e1 = __expf((sacc[mt][j][1] - mx0) * SCALE);
                    float e2 = __expf((sacc[mt][j][2] - mx1) * SCALE);
                    float e3 = __expf((sacc[mt][j][3] - mx1) * SCALE);
                    sacc[mt][j][0] = e0; sacc[mt][j][1] = e1;
                    sacc[mt][j][2] = e2; sacc[mt][j][3] = e3;
                    sum0 += e0 + e1; sum1 += e2 + e3;
                }
                sum0 += __shfl_xor_sync(FULL, sum0, 1);
                sum0 += __shfl_xor_sync(FULL, sum0, 2);
                sum1 += __shfl_xor_sync(FULL, sum1, 1);
                sum1 += __shfl_xor_sync(FULL, sum1, 2);
                inv0[mt] = 1.0f / sum0;
                inv1[mt] = 1.0f / sum1;
            }

            float oacc[2][4][4];
            #pragma unroll
            for (int mt = 0; mt < 2; ++mt)
                #pragma unroll
                for (int j = 0; j < 4; ++j)
                    #pragma unroll
                    for (int q = 0; q < 4; ++q) oacc[mt][j][q] = 0.f;

            const uint32_t vBase =
                (uint32_t)((((lane >> 3) & 1) * 8 + (lane & 7)) * 272 +
                           (head * 32 + (lane >> 4) * 8) * 2);

            #pragma unroll
            for (int t = 0; t < 4; ++t) {
                uint32_t vh[2][4];
                #pragma unroll
                for (int g = 0; g < 2; ++g) {
                    uint32_t ro = vBase + (uint32_t)(t * 16 * 272) + (uint32_t)(g * 32);
                    ldsm4t(vh[g], sb + SV + ro);
                }
                #pragma unroll
                for (int mt = 0; mt < 2; ++mt) {
                    uint32_t ph[4];
                    ph[0] = pkh2(sacc[mt][2 * t][0],     sacc[mt][2 * t][1]);
                    ph[1] = pkh2(sacc[mt][2 * t][2],     sacc[mt][2 * t][3]);
                    ph[2] = pkh2(sacc[mt][2 * t + 1][0], sacc[mt][2 * t + 1][1]);
                    ph[3] = pkh2(sacc[mt][2 * t + 1][2], sacc[mt][2 * t + 1][3]);
                    #pragma unroll
                    for (int j = 0; j < 4; ++j) {
                        const int g = j >> 1, e = (j & 1) * 2;
                        mma16816(oacc[mt][j], ph, vh[g][e], vh[g][e + 1]);
                    }
                }
            }

            // normalize + fp16 A' (token-major) overlaying this window's A tile
            __half* Ap = (__half*)(smem + saI);
            #pragma unroll
            for (int mt = 0; mt < 2; ++mt)
                #pragma unroll
                for (int j = 0; j < 4; ++j) {
                    int ccol = head * 32 + j * 8 + 2 * tig;
                    *(uint32_t*)&Ap[(m0 + mt * 16 + gid) * STRA + ccol] =
                        pkh2(oacc[mt][j][0] * inv0[mt], oacc[mt][j][1] * inv0[mt]);
                    *(uint32_t*)&Ap[(m0 + mt * 16 + gid + 8) * STRA + ccol] =
                        pkh2(oacc[mt][j][2] * inv1[mt], oacc[mt][j][3] * inv1[mt]);
                }
        }
        __syncthreads();

        // ---- Phase 4: proj GEMM (non-trans A' at saI) + bias -> PO ----
        {
            float pacc[2][4][4];
            #pragma unroll
            for (int mt = 0; mt < 2; ++mt)
                #pragma unroll
                for (int j = 0; j < 4; ++j)
                    #pragma unroll
                    for (int q = 0; q < 4; ++q) pacc[mt][j][q] = 0.f;

            #pragma unroll
            for (int kk = 0; kk < 8; ++kk) {
                const uint32_t ka = kk * 32;
                uint32_t ah[2][4];
                ldsm4(ah[0], sb + saI + aOffP[0] + ka);
                ldsm4(ah[1], sb + saI + aOffP[1] + ka);
                const int base = ((nbi * 8 + kk) * 2) * 32 + lane;
                uint4 w0 = __ldg(&g_wfragP[base]);
                uint4 w1 = __ldg(&g_wfragP[base + 32]);
                uint32_t bb[2][4] = {{w0.x, w0.y, w0.z, w0.w}, {w1.x, w1.y, w1.z, w1.w}};
                #pragma unroll
                for (int mt = 0; mt < 2; ++mt)
                    #pragma unroll
                    for (int j = 0; j < 4; ++j) {
                        const int g = j >> 1, e = (j & 1) * 2;
                        mma16816(pacc[mt][j], ah[mt], bb[g][e], bb[g][e + 1]);
                    }
            }
            float* PO = (float*)(smem + SPO);
            #pragma unroll
            for (int mt = 0; mt < 2; ++mt)
                #pragma unroll
                for (int j = 0; j < 4; ++j) {
                    int ccol = nb + j * 8 + 2 * tig;
                    float b0f = __ldg(&bproj[ccol]), b1f = __ldg(&bproj[ccol + 1]);
                    *(float2*)&PO[(m0 + mt * 16 + gid) * STRQ + ccol] =
                        make_float2(pacc[mt][j][0] + b0f, pacc[mt][j][1] + b1f);
                    *(float2*)&PO[(m0 + mt * 16 + gid + 8) * STRQ + ccol] =
                        make_float2(pacc[mt][j][2] + b0f, pacc[mt][j][3] + b1f);
                }
        }
        __syncthreads();

        // ---- Phase 5: scatter ----
        {
            const float* PO = (const float*)(smem + SPO);
            #pragma unroll 4
            for (int it = 0; it < 32; ++it) {
                int ch = ch0 + it;
                out[gbase + (size_t)ch * 65536u] = PO[l8 * STRQ + ch];
            }
        }
        __syncthreads();   // next window's K/V stores overlay PO region
    }
}

extern "C" void kernel_launch(void* const* d_in, const int* in_sizes, int n_in,
                              void* d_out, int out_size) {
    (void)in_sizes; (void)n_in; (void)out_size;
    const float* x     = (const float*)d_in[0];
    const float* wqkv  = (const float*)d_in[1];
    const float* wproj = (const float*)d_in[2];
    const float* bproj = (const float*)d_in[3];
    float* out = (float*)d_out;

    init_weights_kernel<<<32, 256>>>(wqkv, wproj);

    cudaFuncSetAttribute(swin_mma_kernel,
                         cudaFuncAttributeMaxDynamicSharedMemorySize, SMEM_BYTES);
    swin_mma_kernel<<<GRID, 256, SMEM_BYTES>>>(x, bproj, out);
}

// round 14
// speedup vs baseline: 1.0616x; 1.0616x over previous
#include <cuda_runtime.h>
#include <cuda_fp16.h>
#include <cstdint>

// ---------------- problem constants ----------------
#define SCALE 0.1767766952966369f   // 32^-0.5

// ---------------- smem layout (bytes) ----------------
#define STRC 144                     // A-tile channel-major row stride (bytes)
#define SAW  18464                   // per-window A region
#define STRA 136                     // token-major fp16 row stride (halves) for K/V/A'
#define SK   73856                   // K fp16 tile [64][136]
#define SV   91264                   // V fp16 tile
#define SMEM_BYTES 108672

#define NWIN_PER_CTA 4
#define GRID 2048

// ---------------- ptx helpers ----------------
__device__ __forceinline__ uint32_t smem_u32(const void* p) {
    uint32_t a;
    asm("{ .reg .u64 t; cvta.to.shared.u64 t, %1; cvt.u32.u64 %0, t; }" : "=r"(a) : "l"(p));
    return a;
}
__device__ __forceinline__ void ldsm4(uint32_t* r, uint32_t addr) {
    asm volatile("ldmatrix.sync.aligned.m8n8.x4.shared.b16 {%0,%1,%2,%3}, [%4];"
                 : "=r"(r[0]), "=r"(r[1]), "=r"(r[2]), "=r"(r[3]) : "r"(addr));
}
__device__ __forceinline__ void ldsm4t(uint32_t* r, uint32_t addr) {
    asm volatile("ldmatrix.sync.aligned.m8n8.x4.trans.shared.b16 {%0,%1,%2,%3}, [%4];"
                 : "=r"(r[0]), "=r"(r[1]), "=r"(r[2]), "=r"(r[3]) : "r"(addr));
}
__device__ __forceinline__ void mma16816(float* c, const uint32_t* a,
                                         uint32_t b0, uint32_t b1) {
    asm volatile(
        "mma.sync.aligned.m16n8k16.row.col.f32.f16.f16.f32 "
        "{%0,%1,%2,%3}, {%4,%5,%6,%7}, {%8,%9}, {%0,%1,%2,%3};"
        : "+f"(c[0]), "+f"(c[1]), "+f"(c[2]), "+f"(c[3])
        : "r"(a[0]), "r"(a[1]), "r"(a[2]), "r"(a[3]), "r"(b0), "r"(b1));
}
__device__ __forceinline__ uint32_t pkh2(float x, float y) {
    __half2 H = __halves2half2(__float2half_rn(x), __float2half_rn(y));
    return *(uint32_t*)&H;
}

// ---------------- weight B-fragments in canonical m16n8k16 lane layout ----------
__device__ uint4 g_wfragQKV[3 * 4 * 8 * 2 * 32];   // 96 KB
__device__ uint4 g_wfragP[4 * 8 * 2 * 32];         // 32 KB

__global__ void init_weights_kernel(const float* __restrict__ wqkv,
                                    const float* __restrict__ wproj) {
    int t = blockIdx.x * blockDim.x + threadIdx.x;   // 8192 threads
    bool isP = t >= 6144;
    int e = isP ? t - 6144 : t;
    int lane = e & 31, g = (e >> 5) & 1, kk = (e >> 6) & 7, nbi = (e >> 9) & 3;
    int c = isP ? 0 : (e >> 11);
    int gid = lane >> 2, tig = lane & 3;
    int n_a = nbi * 32 + g * 16 + gid;
    int n_b = n_a + 8;
    int k0 = kk * 16 + 2 * tig;
    float w00, w01, w10, w11, w20, w21, w30, w31;
    if (isP) {
        w00 = wproj[k0 * 128 + n_a];       w01 = wproj[(k0 + 1) * 128 + n_a];
        w10 = wproj[(k0 + 8) * 128 + n_a]; w11 = wproj[(k0 + 9) * 128 + n_a];
        w20 = wproj[k0 * 128 + n_b];       w21 = wproj[(k0 + 1) * 128 + n_b];
        w30 = wproj[(k0 + 8) * 128 + n_b]; w31 = wproj[(k0 + 9) * 128 + n_b];
    } else {
        int nb0 = c * 128;
        w00 = wqkv[k0 * 384 + nb0 + n_a];       w01 = wqkv[(k0 + 1) * 384 + nb0 + n_a];
        w10 = wqkv[(k0 + 8) * 384 + nb0 + n_a]; w11 = wqkv[(k0 + 9) * 384 + nb0 + n_a];
        w20 = wqkv[k0 * 384 + nb0 + n_b];       w21 = wqkv[(k0 + 1) * 384 + nb0 + n_b];
        w30 = wqkv[(k0 + 8) * 384 + nb0 + n_b]; w31 = wqkv[(k0 + 9) * 384 + nb0 + n_b];
    }
    uint4 v;
    v.x = pkh2(w00, w01); v.y = pkh2(w10, w11);
    v.z = pkh2(w20, w21); v.w = pkh2(w30, w31);
    (isP ? g_wfragP : g_wfragQKV)[e] = v;
}

// ---------------- main kernel: 256 threads, 2 CTAs/SM, 4 fused windows/CTA ----
__global__ __launch_bounds__(256, 2)
void swin_mma_kernel(const float* __restrict__ x,
                     const float* __restrict__ bproj,
                     float* __restrict__ out) {
    extern __shared__ char smem[];
    const uint32_t sb = smem_u32(smem);
    const int tid  = threadIdx.x;
    const int wid  = tid >> 5;
    const int lane = tid & 31;

    const int bid  = blockIdx.x;
    const int win0 = bid * NWIN_PER_CTA;
    const int b0   = win0 >> 10;
    const int wh0  = (win0 >> 5) & 31;
    const int ww0  = win0 & 31;

    // warp roles: 2 (M) x 4 (N); warp tile 32 rows x 32 cols
    const int m0  = (wid >> 2) * 32;
    const int nbi = wid & 3;
    const int nb  = nbi * 32;
    const int gid = lane >> 2, tig = lane & 3;

    // trans-A per-lane offsets (channel-major A tiles)
    const uint32_t kLane = (uint32_t)(((lane & 7) + ((lane >> 4) & 1) * 8) * STRC);
    uint32_t aT[2], aOffP[2];
    #pragma unroll
    for (int mt = 0; mt < 2; ++mt) {
        aT[mt] = kLane + (uint32_t)((m0 + mt * 16 + ((lane >> 3) & 1) * 8) * 2);
        aOffP[mt] = (uint32_t)((m0 + mt * 16 + ((lane >> 3) & 1) * 8 + (lane & 7)) * 272 +
                               (lane >> 4) * 16);
    }
    const uint32_t bRowOff = (uint32_t)((((lane >> 4) & 1) * 8 + (lane & 7)) * 272);
    const uint32_t bKOff   = (uint32_t)(((lane >> 3) & 1) * 16);

    // direct-scatter constants: token rows handled by this thread in proj
    // t0(mt) = m0 + mt*16 + gid  (gid<8 => cc8 = gid; rr = (m0+mt*16)>>3)
    int ghA[2][2];
    #pragma unroll
    for (int mt = 0; mt < 2; ++mt) {
        int rr0 = (m0 + mt * 16) >> 3;
        ghA[mt][0] = (wh0 * 8 + rr0 + 4) & 255;
        ghA[mt][1] = (wh0 * 8 + rr0 + 1 + 4) & 255;
    }
    // bias (window-invariant per thread)
    float2 pb[4];
    #pragma unroll
    for (int j = 0; j < 4; ++j) {
        int ccol = nb + j * 8 + 2 * tig;
        pb[j] = make_float2(__ldg(&bproj[ccol]), __ldg(&bproj[ccol + 1]));
    }
    float* outb = out + (size_t)b0 * (128u * 65536u);

    // ---- Prologue: fused 4-window gather, fp32 -> fp16, channel-major A tiles
    {
        const int s0   = ww0 * 8 + 4;
        const int sub  = lane >> 3, li = lane & 7;
        const int wiA  = li >> 1, cc8g = (li & 1) * 4;
        const int gwb  = (s0 + li * 4) & 255;
        const float* xb = x + (size_t)b0 * (128u * 65536u);
        #pragma unroll 4
        for (int it = 0; it < 32; ++it) {
            int pairIdx = wid * 128 + it * 4 + sub;
            int ch = pairIdx >> 3, rr = pairIdx & 7;
            int gh = (wh0 * 8 + rr + 4) & 255;
            float4 v = __ldg((const float4*)(xb + (size_t)ch * 65536u + gh * 256 + gwb));
            int token = rr * 8 + cc8g;
            uint2 hv;
            hv.x = pkh2(v.x, v.y);
            hv.y = pkh2(v.z, v.w);
            *(uint2*)(smem + wiA * SAW + ch * STRC + token * 2) = hv;
        }
    }
    __syncthreads();

    for (int i = 0; i < NWIN_PER_CTA; ++i) {
        const uint32_t saI = (uint32_t)(i * SAW);
        const int ww = ww0 + i;
        const int gwP = (ww * 8 + gid + 4) & 255;   // proj-scatter column for this thread

        // ---- Phase 2a: Q+K GEMM (trans-A from channel-major tile) ----
        uint32_t qf[2][2][4];
        {
            float accA[2][2][4][4];
            #pragma unroll
            for (int c = 0; c < 2; ++c)
                #pragma unroll
                for (int mt = 0; mt < 2; ++mt)
                    #pragma unroll
                    for (int j = 0; j < 4; ++j)
                        #pragma unroll
                        for (int q = 0; q < 4; ++q) accA[c][mt][j][q] = 0.f;

            #pragma unroll
            for (int kk = 0; kk < 8; ++kk) {
                uint32_t ah[2][4];
                ldsm4t(ah[0], sb + saI + aT[0] + kk * (16 * STRC));
                ldsm4t(ah[1], sb + saI + aT[1] + kk * (16 * STRC));
                #pragma unroll
                for (int c = 0; c < 2; ++c) {
                    const int base = (((c * 4 + nbi) * 8 + kk) * 2) * 32 + lane;
                    uint4 w0 = __ldg(&g_wfragQKV[base]);
                    uint4 w1 = __ldg(&g_wfragQKV[base + 32]);
                    uint32_t bb[2][4] = {{w0.x, w0.y, w0.z, w0.w},
                                         {w1.x, w1.y, w1.z, w1.w}};
                    #pragma unroll
                    for (int mt = 0; mt < 2; ++mt)
                        #pragma unroll
                        for (int j = 0; j < 4; ++j) {
                            const int g = j >> 1, e = (j & 1) * 2;
                            mma16816(accA[c][mt][j], ah[mt], bb[g][e], bb[g][e + 1]);
                        }
                }
            }

            #pragma unroll
            for (int mt = 0; mt < 2; ++mt)
                #pragma unroll
                for (int kk2 = 0; kk2 < 2; ++kk2) {
                    qf[mt][kk2][0] = pkh2(accA[0][mt][2 * kk2][0],     accA[0][mt][2 * kk2][1]);
                    qf[mt][kk2][1] = pkh2(accA[0][mt][2 * kk2][2],     accA[0][mt][2 * kk2][3]);
                    qf[mt][kk2][2] = pkh2(accA[0][mt][2 * kk2 + 1][0], accA[0][mt][2 * kk2 + 1][1]);
                    qf[mt][kk2][3] = pkh2(accA[0][mt][2 * kk2 + 1][2], accA[0][mt][2 * kk2 + 1][3]);
                }

            __half* T = (__half*)(smem + SK);
            #pragma unroll
            for (int mt = 0; mt < 2; ++mt)
                #pragma unroll
                for (int j = 0; j < 4; ++j) {
                    int ccol = nb + j * 8 + 2 * tig;
                    *(uint32_t*)&T[(m0 + mt * 16 + gid) * STRA + ccol] =
                        pkh2(accA[1][mt][j][0], accA[1][mt][j][1]);
                    *(uint32_t*)&T[(m0 + mt * 16 + gid + 8) * STRA + ccol] =
                        pkh2(accA[1][mt][j][2], accA[1][mt][j][3]);
                }
        }

        // ---- Phase 2b: V GEMM ----
        {
            float accV[2][4][4];
            #pragma unroll
            for (int mt = 0; mt < 2; ++mt)
                #pragma unroll
                for (int j = 0; j < 4; ++j)
                    #pragma unroll
                    for (int q = 0; q < 4; ++q) accV[mt][j][q] = 0.f;

            #pragma unroll
            for (int kk = 0; kk < 8; ++kk) {
                uint32_t ah[2][4];
                ldsm4t(ah[0], sb + saI + aT[0] + kk * (16 * STRC));
                ldsm4t(ah[1], sb + saI + aT[1] + kk * (16 * STRC));
                const int base = (((2 * 4 + nbi) * 8 + kk) * 2) * 32 + lane;
                uint4 w0 = __ldg(&g_wfragQKV[base]);
                uint4 w1 = __ldg(&g_wfragQKV[base + 32]);
                uint32_t bb[2][4] = {{w0.x, w0.y, w0.z, w0.w}, {w1.x, w1.y, w1.z, w1.w}};
                #pragma unroll
                for (int mt = 0; mt < 2; ++mt)
                    #pragma unroll
                    for (int j = 0; j < 4; ++j) {
                        const int g = j >> 1, e = (j & 1) * 2;
                        mma16816(accV[mt][j], ah[mt], bb[g][e], bb[g][e + 1]);
                    }
            }
            __half* T = (__half*)(smem + SV);
            #pragma unroll
            for (int mt = 0; mt < 2; ++mt)
                #pragma unroll
                for (int j = 0; j < 4; ++j) {
                    int ccol = nb + j * 8 + 2 * tig;
                    *(uint32_t*)&T[(m0 + mt * 16 + gid) * STRA + ccol] =
                        pkh2(accV[mt][j][0], accV[mt][j][1]);
                    *(uint32_t*)&T[(m0 + mt * 16 + gid + 8) * STRA + ccol] =
                        pkh2(accV[mt][j][2], accV[mt][j][3]);
                }
        }
        __syncthreads();   // K/V ready

        // ---- Phase 3: attention (1-pass fp16), A' token-major overlays A_i ----
        {
            const int head = nbi;

            float sacc[2][8][4];
            #pragma unroll
            for (int mt = 0; mt < 2; ++mt)
                #pragma unroll
                for (int j = 0; j < 8; ++j)
                    #pragma unroll
                    for (int q = 0; q < 4; ++q) sacc[mt][j][q] = 0.f;

            #pragma unroll
            for (int kk2 = 0; kk2 < 2; ++kk2) {
                const uint32_t ka = kk2 * 32;
                uint32_t kh[4][4];
                #pragma unroll
                for (int g = 0; g < 4; ++g) {
                    uint32_t ro = (uint32_t)(g * 16 * 272) + bRowOff + bKOff +
                                  (uint32_t)(head * 64) + ka;
                    ldsm4(kh[g], sb + SK + ro);
                }
                #pragma unroll
                for (int mt = 0; mt < 2; ++mt)
                    #pragma unroll
                    for (int j = 0; j < 8; ++j) {
                        const int g = j >> 1, e = (j & 1) * 2;
                        mma16816(sacc[mt][j], qf[mt][kk2], kh[g][e], kh[g][e + 1]);
                    }
            }

            const unsigned FULL = 0xffffffffu;
            float inv0[2], inv1[2];
            #pragma unroll
            for (int mt = 0; mt < 2; ++mt) {
                float mx0 = -1e30f, mx1 = -1e30f;
                #pragma unroll
                for (int j = 0; j < 8; ++j) {
                    mx0 = fmaxf(mx0, fmaxf(sacc[mt][j][0], sacc[mt][j][1]));
                    mx1 = fmaxf(mx1, fmaxf(sacc[mt][j][2], sacc[mt][j][3]));
                }
                mx0 = fmaxf(mx0, __shfl_xor_sync(FULL, mx0, 1));
                mx0 = fmaxf(mx0, __shfl_xor_sync(FULL, mx0, 2));
                mx1 = fmaxf(mx1, __shfl_xor_sync(FULL, mx1, 1));
                mx1 = fmaxf(mx1, __shfl_xor_sync(FULL, mx1, 2));
                float sum0 = 0.f, sum1 = 0.f;
                #pragma unroll
                for (int j = 0; j < 8; ++j) {
                    float e0 = __expf((sacc[mt][j][0] - mx0) * SCALE);
                    float e1 = __expf((sacc[mt][j][1] - mx0) * SCALE);
                    float e2 = __expf((sacc[mt][j][2] - mx1) * SCALE);
                    float e3 = __expf((sacc[mt][j][3] - mx1) * SCALE);
                    sacc[mt][j][0] = e0; sacc[mt][j][1] = e1;
                    sacc[mt][j][2] = e2; sacc[mt][j][3] = e3;
                    sum0 += e0 + e1; sum1 += e2 + e3;
                }
                sum0 += __shfl_xor_sync(FULL, sum0, 1);
                sum0 += __shfl_xor_sync(FULL, sum0, 2);
                sum1 += __shfl_xor_sync(FULL, sum1, 1);
                sum1 += __shfl_xor_sync(FULL, sum1, 2);
                inv0[mt] = 1.0f / sum0;
                inv1[mt] = 1.0f / sum1;
            }

            float oacc[2][4][4];
            #pragma unroll
            for (int mt = 0; mt < 2; ++mt)
                #pragma unroll
                for (int j = 0; j < 4; ++j)
                    #pragma unroll
                    for (int q = 0; q < 4; ++q) oacc[mt][j][q] = 0.f;

            const uint32_t vBase =
                (uint32_t)((((lane >> 3) & 1) * 8 + (lane & 7)) * 272 +
                           (head * 32 + (lane >> 4) * 8) * 2);

            #pragma unroll
            for (int t = 0; t < 4; ++t) {
                uint32_t vh[2][4];
                #pragma unroll
                for (int g = 0; g < 2; ++g) {
                    uint32_t ro = vBase + (uint32_t)(t * 16 * 272) + (uint32_t)(g * 32);
                    ldsm4t(vh[g], sb + SV + ro);
                }
                #pragma unroll
                for (int mt = 0; mt < 2; ++mt) {
                    uint32_t ph[4];
                    ph[0] = pkh2(sacc[mt][2 * t][0],     sacc[mt][2 * t][1]);
                    ph[1] = pkh2(sacc[mt][2 * t][2],     sacc[mt][2 * t][3]);
                    ph[2] = pkh2(sacc[mt][2 * t + 1][0], sacc[mt][2 * t + 1][1]);
                    ph[3] = pkh2(sacc[mt][2 * t + 1][2], sacc[mt][2 * t + 1][3]);
                    #pragma unroll
                    for (int j = 0; j < 4; ++j) {
                        const int g = j >> 1, e = (j & 1) * 2;
                        mma16816(oacc[mt][j], ph, vh[g][e], vh[g][e + 1]);
                    }
                }
            }

            // normalize + fp16 A' (token-major) overlaying this window's A tile
            __half* Ap = (__half*)(smem + saI);
            #pragma unroll
            for (int mt = 0; mt < 2; ++mt)
                #pragma unroll
                for (int j = 0; j < 4; ++j) {
                    int ccol = head * 32 + j * 8 + 2 * tig;
                    *(uint32_t*)&Ap[(m0 + mt * 16 + gid) * STRA + ccol] =
                        pkh2(oacc[mt][j][0] * inv0[mt], oacc[mt][j][1] * inv0[mt]);
                    *(uint32_t*)&Ap[(m0 + mt * 16 + gid + 8) * STRA + ccol] =
                        pkh2(oacc[mt][j][2] * inv1[mt], oacc[mt][j][3] * inv1[mt]);
                }
        }
        __syncthreads();   // A' ready (also fences all K/V reads of this window)

        // ---- Phase 4: proj GEMM + bias, scatter DIRECT from accumulators ----
        {
            float pacc[2][4][4];
            #pragma unroll
            for (int mt = 0; mt < 2; ++mt)
                #pragma unroll
                for (int j = 0; j < 4; ++j)
                    #pragma unroll
                    for (int q = 0; q < 4; ++q) pacc[mt][j][q] = 0.f;

            #pragma unroll
            for (int kk = 0; kk < 8; ++kk) {
                const uint32_t ka = kk * 32;
                uint32_t ah[2][4];
                ldsm4(ah[0], sb + saI + aOffP[0] + ka);
                ldsm4(ah[1], sb + saI + aOffP[1] + ka);
                const int base = ((nbi * 8 + kk) * 2) * 32 + lane;
                uint4 w0 = __ldg(&g_wfragP[base]);
                uint4 w1 = __ldg(&g_wfragP[base + 32]);
                uint32_t bb[2][4] = {{w0.x, w0.y, w0.z, w0.w}, {w1.x, w1.y, w1.z, w1.w}};
                #pragma unroll
                for (int mt = 0; mt < 2; ++mt)
                    #pragma unroll
                    for (int j = 0; j < 4; ++j) {
                        const int g = j >> 1, e = (j & 1) * 2;
                        mma16816(pacc[mt][j], ah[mt], bb[g][e], bb[g][e + 1]);
                    }
            }

            // direct scatter: rows t0 = m0+mt*16+gid (q0,q1), t1 = t0+8 (q2,q3)
            #pragma unroll
            for (int mt = 0; mt < 2; ++mt) {
                const size_t a0 = (size_t)(ghA[mt][0] * 256 + gwP);
                const size_t a1 = (size_t)(ghA[mt][1] * 256 + gwP);
                #pragma unroll
                for (int j = 0; j < 4; ++j) {
                    const size_t cOff = (size_t)(nb + j * 8 + 2 * tig) * 65536u;
                    outb[a0 + cOff]          = pacc[mt][j][0] + pb[j].x;
                    outb[a0 + cOff + 65536u] = pacc[mt][j][1] + pb[j].y;
                    outb[a1 + cOff]          = pacc[mt][j][2] + pb[j].x;
                    outb[a1 + cOff + 65536u] = pacc[mt][j][3] + pb[j].y;
                }
            }
        }
        // no sync: next window's K/V stores (SK/SV) are disjoint from A'(saI)
        // reads here, and this window's K/V reads were fenced by the post-A' sync
    }
}

extern "C" void kernel_launch(void* const* d_in, const int* in_sizes, int n_in,
                              void* d_out, int out_size) {
    (void)in_sizes; (void)n_in; (void)out_size;
    const float* x     = (const float*)d_in[0];
    const float* wqkv  = (const float*)d_in[1];
    const float* wproj = (const float*)d_in[2];
    const float* bproj = (const float*)d_in[3];
    float* out = (float*)d_out;

    init_weights_kernel<<<32, 256>>>(wqkv, wproj);

    cudaFuncSetAttribute(swin_mma_kernel,
                         cudaFuncAttributeMaxDynamicSharedMemorySize, SMEM_BYTES);
    swin_mma_kernel<<<GRID, 256, SMEM_BYTES>>>(x, bproj, out);
}

// round 15
// speedup vs baseline: 1.0690x; 1.0069x over previous
#include <cuda_runtime.h>
#include <cuda_fp16.h>
#include <cstdint>

// ---------------- problem constants ----------------
#define SCALE 0.1767766952966369f   // 32^-0.5

// ---------------- smem layout (bytes) ----------------
#define STRC 144                     // A-tile channel-major row stride (bytes)
#define SAW  18464                   // per-window A region
#define STRA 136                     // token-major fp16 row stride (halves) for K/V/A'
#define SK   73856                   // K fp16 tile [64][136]
#define SV   91264                   // V fp16 tile
#define SMEM_BYTES 108672

#define NWIN_PER_CTA 4
#define GRID 2048

// ---------------- ptx helpers ----------------
__device__ __forceinline__ uint32_t smem_u32(const void* p) {
    uint32_t a;
    asm("{ .reg .u64 t; cvta.to.shared.u64 t, %1; cvt.u32.u64 %0, t; }" : "=r"(a) : "l"(p));
    return a;
}
__device__ __forceinline__ void ldsm4(uint32_t* r, uint32_t addr) {
    asm volatile("ldmatrix.sync.aligned.m8n8.x4.shared.b16 {%0,%1,%2,%3}, [%4];"
                 : "=r"(r[0]), "=r"(r[1]), "=r"(r[2]), "=r"(r[3]) : "r"(addr));
}
__device__ __forceinline__ void ldsm4t(uint32_t* r, uint32_t addr) {
    asm volatile("ldmatrix.sync.aligned.m8n8.x4.trans.shared.b16 {%0,%1,%2,%3}, [%4];"
                 : "=r"(r[0]), "=r"(r[1]), "=r"(r[2]), "=r"(r[3]) : "r"(addr));
}
__device__ __forceinline__ void mma16816(float* c, const uint32_t* a,
                                         uint32_t b0, uint32_t b1) {
    asm volatile(
        "mma.sync.aligned.m16n8k16.row.col.f32.f16.f16.f32 "
        "{%0,%1,%2,%3}, {%4,%5,%6,%7}, {%8,%9}, {%0,%1,%2,%3};"
        : "+f"(c[0]), "+f"(c[1]), "+f"(c[2]), "+f"(c[3])
        : "r"(a[0]), "r"(a[1]), "r"(a[2]), "r"(a[3]), "r"(b0), "r"(b1));
}
__device__ __forceinline__ uint32_t pkh2(float x, float y) {
    __half2 H = __halves2half2(__float2half_rn(x), __float2half_rn(y));
    return *(uint32_t*)&H;
}
#define BAR_SYNC(id, cnt) \
    asm volatile("bar.sync %0, %1;" :: "r"(id), "r"(cnt) : "memory")

// ---------------- weight B-fragments in canonical m16n8k16 lane layout ----------
__device__ uint4 g_wfragQKV[3 * 4 * 8 * 2 * 32];   // 96 KB
__device__ uint4 g_wfragP[4 * 8 * 2 * 32];         // 32 KB

__global__ void init_weights_kernel(const float* __restrict__ wqkv,
                                    const float* __restrict__ wproj) {
    int t = blockIdx.x * blockDim.x + threadIdx.x;   // 8192 threads
    bool isP = t >= 6144;
    int e = isP ? t - 6144 : t;
    int lane = e & 31, g = (e >> 5) & 1, kk = (e >> 6) & 7, nbi = (e >> 9) & 3;
    int c = isP ? 0 : (e >> 11);
    int gid = lane >> 2, tig = lane & 3;
    int n_a = nbi * 32 + g * 16 + gid;
    int n_b = n_a + 8;
    int k0 = kk * 16 + 2 * tig;
    float w00, w01, w10, w11, w20, w21, w30, w31;
    if (isP) {
        w00 = wproj[k0 * 128 + n_a];       w01 = wproj[(k0 + 1) * 128 + n_a];
        w10 = wproj[(k0 + 8) * 128 + n_a]; w11 = wproj[(k0 + 9) * 128 + n_a];
        w20 = wproj[k0 * 128 + n_b];       w21 = wproj[(k0 + 1) * 128 + n_b];
        w30 = wproj[(k0 + 8) * 128 + n_b]; w31 = wproj[(k0 + 9) * 128 + n_b];
    } else {
        int nb0 = c * 128;
        w00 = wqkv[k0 * 384 + nb0 + n_a];       w01 = wqkv[(k0 + 1) * 384 + nb0 + n_a];
        w10 = wqkv[(k0 + 8) * 384 + nb0 + n_a]; w11 = wqkv[(k0 + 9) * 384 + nb0 + n_a];
        w20 = wqkv[k0 * 384 + nb0 + n_b];       w21 = wqkv[(k0 + 1) * 384 + nb0 + n_b];
        w30 = wqkv[(k0 + 8) * 384 + nb0 + n_b]; w31 = wqkv[(k0 + 9) * 384 + nb0 + n_b];
    }
    uint4 v;
    v.x = pkh2(w00, w01); v.y = pkh2(w10, w11);
    v.z = pkh2(w20, w21); v.w = pkh2(w30, w31);
    (isP ? g_wfragP : g_wfragQKV)[e] = v;
}

// ---------------- main kernel: 256 threads, 2 CTAs/SM, 4 fused windows/CTA ----
__global__ __launch_bounds__(256, 2)
void swin_mma_kernel(const float* __restrict__ x,
                     const float* __restrict__ bproj,
                     float* __restrict__ out) {
    extern __shared__ char smem[];
    const uint32_t sb = smem_u32(smem);
    const int tid  = threadIdx.x;
    const int wid  = tid >> 5;
    const int lane = tid & 31;

    const int bid  = blockIdx.x;
    const int win0 = bid * NWIN_PER_CTA;
    const int b0   = win0 >> 10;
    const int wh0  = (win0 >> 5) & 31;
    const int ww0  = win0 & 31;

    // warp roles: 2 (M) x 4 (N); warp tile 32 rows x 32 cols
    const int m0  = (wid >> 2) * 32;
    const int nbi = wid & 3;
    const int nb  = nbi * 32;
    const int gid = lane >> 2, tig = lane & 3;

    // named-barrier ids: pair {nbi, nbi+4} -> 1..4; m-group -> 5..6
    const int pairBar = 1 + nbi;
    const int mgBar   = 5 + (wid >> 2);

    // trans-A per-lane offsets (channel-major A tiles)
    const uint32_t kLane = (uint32_t)(((lane & 7) + ((lane >> 4) & 1) * 8) * STRC);
    uint32_t aT[2], aOffP[2];
    #pragma unroll
    for (int mt = 0; mt < 2; ++mt) {
        aT[mt] = kLane + (uint32_t)((m0 + mt * 16 + ((lane >> 3) & 1) * 8) * 2);
        aOffP[mt] = (uint32_t)((m0 + mt * 16 + ((lane >> 3) & 1) * 8 + (lane & 7)) * 272 +
                               (lane >> 4) * 16);
    }
    const uint32_t bRowOff = (uint32_t)((((lane >> 4) & 1) * 8 + (lane & 7)) * 272);
    const uint32_t bKOff   = (uint32_t)(((lane >> 3) & 1) * 16);

    // direct-scatter constants
    int ghA[2][2];
    #pragma unroll
    for (int mt = 0; mt < 2; ++mt) {
        int rr0 = (m0 + mt * 16) >> 3;
        ghA[mt][0] = (wh0 * 8 + rr0 + 4) & 255;
        ghA[mt][1] = (wh0 * 8 + rr0 + 1 + 4) & 255;
    }
    float2 pb[4];
    #pragma unroll
    for (int j = 0; j < 4; ++j) {
        int ccol = nb + j * 8 + 2 * tig;
        pb[j] = make_float2(__ldg(&bproj[ccol]), __ldg(&bproj[ccol + 1]));
    }
    float* outb = out + (size_t)b0 * (128u * 65536u);

    // ---- Prologue: fused 4-window gather, fp32 -> fp16, channel-major A tiles
    {
        const int s0   = ww0 * 8 + 4;
        const int sub  = lane >> 3, li = lane & 7;
        const int wiA  = li >> 1, cc8g = (li & 1) * 4;
        const int gwb  = (s0 + li * 4) & 255;
        const float* xb = x + (size_t)b0 * (128u * 65536u);
        #pragma unroll 4
        for (int it = 0; it < 32; ++it) {
            int pairIdx = wid * 128 + it * 4 + sub;
            int ch = pairIdx >> 3, rr = pairIdx & 7;
            int gh = (wh0 * 8 + rr + 4) & 255;
            float4 v = __ldg((const float4*)(xb + (size_t)ch * 65536u + gh * 256 + gwb));
            int token = rr * 8 + cc8g;
            uint2 hv;
            hv.x = pkh2(v.x, v.y);
            hv.y = pkh2(v.z, v.w);
            *(uint2*)(smem + wiA * SAW + ch * STRC + token * 2) = hv;
        }
    }
    __syncthreads();

    for (int i = 0; i < NWIN_PER_CTA; ++i) {
        const uint32_t saI = (uint32_t)(i * SAW);
        const int ww = ww0 + i;
        const int gwP = (ww * 8 + gid + 4) & 255;

        // ---- Phase 2a: Q+K GEMM (trans-A from channel-major tile) ----
        uint32_t qf[2][2][4];
        {
            float accA[2][2][4][4];
            #pragma unroll
            for (int c = 0; c < 2; ++c)
                #pragma unroll
                for (int mt = 0; mt < 2; ++mt)
                    #pragma unroll
                    for (int j = 0; j < 4; ++j)
                        #pragma unroll
                        for (int q = 0; q < 4; ++q) accA[c][mt][j][q] = 0.f;

            #pragma unroll
            for (int kk = 0; kk < 8; ++kk) {
                uint32_t ah[2][4];
                ldsm4t(ah[0], sb + saI + aT[0] + kk * (16 * STRC));
                ldsm4t(ah[1], sb + saI + aT[1] + kk * (16 * STRC));
                #pragma unroll
                for (int c = 0; c < 2; ++c) {
                    const int base = (((c * 4 + nbi) * 8 + kk) * 2) * 32 + lane;
                    uint4 w0 = __ldg(&g_wfragQKV[base]);
                    uint4 w1 = __ldg(&g_wfragQKV[base + 32]);
                    uint32_t bb[2][4] = {{w0.x, w0.y, w0.z, w0.w},
                                         {w1.x, w1.y, w1.z, w1.w}};
                    #pragma unroll
                    for (int mt = 0; mt < 2; ++mt)
                        #pragma unroll
                        for (int j = 0; j < 4; ++j) {
                            const int g = j >> 1, e = (j & 1) * 2;
                            mma16816(accA[c][mt][j], ah[mt], bb[g][e], bb[g][e + 1]);
                        }
                }
            }

            #pragma unroll
            for (int mt = 0; mt < 2; ++mt)
                #pragma unroll
                for (int kk2 = 0; kk2 < 2; ++kk2) {
                    qf[mt][kk2][0] = pkh2(accA[0][mt][2 * kk2][0],     accA[0][mt][2 * kk2][1]);
                    qf[mt][kk2][1] = pkh2(accA[0][mt][2 * kk2][2],     accA[0][mt][2 * kk2][3]);
                    qf[mt][kk2][2] = pkh2(accA[0][mt][2 * kk2 + 1][0], accA[0][mt][2 * kk2 + 1][1]);
                    qf[mt][kk2][3] = pkh2(accA[0][mt][2 * kk2 + 1][2], accA[0][mt][2 * kk2 + 1][3]);
                }

            __half* T = (__half*)(smem + SK);
            #pragma unroll
            for (int mt = 0; mt < 2; ++mt)
                #pragma unroll
                for (int j = 0; j < 4; ++j) {
                    int ccol = nb + j * 8 + 2 * tig;
                    *(uint32_t*)&T[(m0 + mt * 16 + gid) * STRA + ccol] =
                        pkh2(accA[1][mt][j][0], accA[1][mt][j][1]);
                    *(uint32_t*)&T[(m0 + mt * 16 + gid + 8) * STRA + ccol] =
                        pkh2(accA[1][mt][j][2], accA[1][mt][j][3]);
                }
        }

        // ---- Phase 2b: V GEMM ----
        {
            float accV[2][4][4];
            #pragma unroll
            for (int mt = 0; mt < 2; ++mt)
                #pragma unroll
                for (int j = 0; j < 4; ++j)
                    #pragma unroll
                    for (int q = 0; q < 4; ++q) accV[mt][j][q] = 0.f;

            #pragma unroll
            for (int kk = 0; kk < 8; ++kk) {
                uint32_t ah[2][4];
                ldsm4t(ah[0], sb + saI + aT[0] + kk * (16 * STRC));
                ldsm4t(ah[1], sb + saI + aT[1] + kk * (16 * STRC));
                const int base = (((2 * 4 + nbi) * 8 + kk) * 2) * 32 + lane;
                uint4 w0 = __ldg(&g_wfragQKV[base]);
                uint4 w1 = __ldg(&g_wfragQKV[base + 32]);
                uint32_t bb[2][4] = {{w0.x, w0.y, w0.z, w0.w}, {w1.x, w1.y, w1.z, w1.w}};
                #pragma unroll
                for (int mt = 0; mt < 2; ++mt)
                    #pragma unroll
                    for (int j = 0; j < 4; ++j) {
                        const int g = j >> 1, e = (j & 1) * 2;
                        mma16816(accV[mt][j], ah[mt], bb[g][e], bb[g][e + 1]);
                    }
            }
            __half* T = (__half*)(smem + SV);
            #pragma unroll
            for (int mt = 0; mt < 2; ++mt)
                #pragma unroll
                for (int j = 0; j < 4; ++j) {
                    int ccol = nb + j * 8 + 2 * tig;
                    *(uint32_t*)&T[(m0 + mt * 16 + gid) * STRA + ccol] =
                        pkh2(accV[mt][j][0], accV[mt][j][1]);
                    *(uint32_t*)&T[(m0 + mt * 16 + gid + 8) * STRA + ccol] =
                        pkh2(accV[mt][j][2], accV[mt][j][3]);
                }
        }
        // CTA-wide: K/V ready AND all channel-major A(i) reads complete
        // (required: A' token-major writes below alias the A(i) region)
        __syncthreads();

        // ---- Phase 3: attention (1-pass fp16), A' token-major overlays A_i ----
        {
            const int head = nbi;

            float sacc[2][8][4];
            #pragma unroll
            for (int mt = 0; mt < 2; ++mt)
                #pragma unroll
                for (int j = 0; j < 8; ++j)
                    #pragma unroll
                    for (int q = 0; q < 4; ++q) sacc[mt][j][q] = 0.f;

            #pragma unroll
            for (int kk2 = 0; kk2 < 2; ++kk2) {
                const uint32_t ka = kk2 * 32;
                uint32_t kh[4][4];
                #pragma unroll
                for (int g = 0; g < 4; ++g) {
                    uint32_t ro = (uint32_t)(g * 16 * 272) + bRowOff + bKOff +
                                  (uint32_t)(head * 64) + ka;
                    ldsm4(kh[g], sb + SK + ro);
                }
                #pragma unroll
                for (int mt = 0; mt < 2; ++mt)
                    #pragma unroll
                    for (int j = 0; j < 8; ++j) {
                        const int g = j >> 1, e = (j & 1) * 2;
                        mma16816(sacc[mt][j], qf[mt][kk2], kh[g][e], kh[g][e + 1]);
                    }
            }

            const unsigned FULL = 0xffffffffu;
            float inv0[2], inv1[2];
            #pragma unroll
            for (int mt = 0; mt < 2; ++mt) {
                float mx0 = -1e30f, mx1 = -1e30f;
                #pragma unroll
                for (int j = 0; j < 8; ++j) {
                    mx0 = fmaxf(mx0, fmaxf(sacc[mt][j][0], sacc[mt][j][1]));
                    mx1 = fmaxf(mx1, fmaxf(sacc[mt][j][2], sacc[mt][j][3]));
                }
                mx0 = fmaxf(mx0, __shfl_xor_sync(FULL, mx0, 1));
                mx0 = fmaxf(mx0, __shfl_xor_sync(FULL, mx0, 2));
                mx1 = fmaxf(mx1, __shfl_xor_sync(FULL, mx1, 1));
                mx1 = fmaxf(mx1, __shfl_xor_sync(FULL, mx1, 2));
                float sum0 = 0.f, sum1 = 0.f;
                #pragma unroll
                for (int j = 0; j < 8; ++j) {
                    float e0 = __expf((sacc[mt][j][0] - mx0) * SCALE);
                    float e1 = __expf((sacc[mt][j][1] - mx0) * SCALE);
                    float e2 = __expf((sacc[mt][j][2] - mx1) * SCALE);
                    float e3 = __expf((sacc[mt][j][3] - mx1) * SCALE);
                    sacc[mt][j][0] = e0; sacc[mt][j][1] = e1;
                    sacc[mt][j][2] = e2; sacc[mt][j][3] = e3;
                    sum0 += e0 + e1; sum1 += e2 + e3;
                }
                sum0 += __shfl_xor_sync(FULL, sum0, 1);
                sum0 += __shfl_xor_sync(FULL, sum0, 2);
                sum1 += __shfl_xor_sync(FULL, sum1, 1);
                sum1 += __shfl_xor_sync(FULL, sum1, 2);
                inv0[mt] = 1.0f / sum0;
                inv1[mt] = 1.0f / sum1;
            }

            float oacc[2][4][4];
            #pragma unroll
            for (int mt = 0; mt < 2; ++mt)
                #pragma unroll
                for (int j = 0; j < 4; ++j)
                    #pragma unroll
                    for (int q = 0; q < 4; ++q) oacc[mt][j][q] = 0.f;

            const uint32_t vBase =
                (uint32_t)((((lane >> 3) & 1) * 8 + (lane & 7)) * 272 +
                           (head * 32 + (lane >> 4) * 8) * 2);

            #pragma unroll
            for (int t = 0; t < 4; ++t) {
                uint32_t vh[2][4];
                #pragma unroll
                for (int g = 0; g < 2; ++g) {
                    uint32_t ro = vBase + (uint32_t)(t * 16 * 272) + (uint32_t)(g * 32);
                    ldsm4t(vh[g], sb + SV + ro);
                }
                #pragma unroll
                for (int mt = 0; mt < 2; ++mt) {
                    uint32_t ph[4];
                    ph[0] = pkh2(sacc[mt][2 * t][0],     sacc[mt][2 * t][1]);
                    ph[1] = pkh2(sacc[mt][2 * t][2],     sacc[mt][2 * t][3]);
                    ph[2] = pkh2(sacc[mt][2 * t + 1][0], sacc[mt][2 * t + 1][1]);
                    ph[3] = pkh2(sacc[mt][2 * t + 1][2], sacc[mt][2 * t + 1][3]);
                    #pragma unroll
                    for (int j = 0; j < 4; ++j) {
                        const int g = j >> 1, e = (j & 1) * 2;
                        mma16816(oacc[mt][j], ph, vh[g][e], vh[g][e + 1]);
                    }
                }
            }

            // pair barrier: both K/V readers of columns nb are done ->
            // safe for this pair to overwrite K/V next window
            if (i + 1 < NWIN_PER_CTA) BAR_SYNC(pairBar, 64);

            // normalize + fp16 A' (token-major) overlaying this window's A tile
            __half* Ap = (__half*)(smem + saI);
            #pragma unroll
            for (int mt = 0; mt < 2; ++mt)
                #pragma unroll
                for (int j = 0; j < 4; ++j) {
                    int ccol = head * 32 + j * 8 + 2 * tig;
                    *(uint32_t*)&Ap[(m0 + mt * 16 + gid) * STRA + ccol] =
                        pkh2(oacc[mt][j][0] * inv0[mt], oacc[mt][j][1] * inv0[mt]);
                    *(uint32_t*)&Ap[(m0 + mt * 16 + gid + 8) * STRA + ccol] =
                        pkh2(oacc[mt][j][2] * inv1[mt], oacc[mt][j][3] * inv1[mt]);
                }
        }
        // m-group barrier: A' rows m0..m0+31 (written by this 4-warp m-group)
        // visible before proj reads them
        BAR_SYNC(mgBar, 128);

        // ---- Phase 4: proj GEMM + bias, scatter DIRECT from accumulators ----
        {
            float pacc[2][4][4];
            #pragma unroll
            for (int mt = 0; mt < 2; ++mt)
                #pragma unroll
                for (int j = 0; j < 4; ++j)
                    #pragma unroll
                    for (int q = 0; q < 4; ++q) pacc[mt][j][q] = 0.f;

            #pragma unroll
            for (int kk = 0; kk < 8; ++kk) {
                const uint32_t ka = kk * 32;
                uint32_t ah[2][4];
                ldsm4(ah[0], sb + saI + aOffP[0] + ka);
                ldsm4(ah[1], sb + saI + aOffP[1] + ka);
                const int base = ((nbi * 8 + kk) * 2) * 32 + lane;
                uint4 w0 = __ldg(&g_wfragP[base]);
                uint4 w1 = __ldg(&g_wfragP[base + 32]);
                uint32_t bb[2][4] = {{w0.x, w0.y, w0.z, w0.w}, {w1.x, w1.y, w1.z, w1.w}};
                #pragma unroll
                for (int mt = 0; mt < 2; ++mt)
                    #pragma unroll
                    for (int j = 0; j < 4; ++j) {
                        const int g = j >> 1, e = (j & 1) * 2;
                        mma16816(pacc[mt][j], ah[mt], bb[g][e], bb[g][e + 1]);
                    }
            }

            // direct scatter: rows t0 = m0+mt*16+gid (q0,q1), t1 = t0+8 (q2,q3)
            #pragma unroll
            for (int mt = 0; mt < 2; ++mt) {
                const size_t a0 = (size_t)(ghA[mt][0] * 256 + gwP);
                const size_t a1 = (size_t)(ghA[mt][1] * 256 + gwP);
                #pragma unroll
                for (int j = 0; j < 4; ++j) {
                    const size_t cOff = (size_t)(nb + j * 8 + 2 * tig) * 65536u;
                    outb[a0 + cOff]          = pacc[mt][j][0] + pb[j].x;
                    outb[a0 + cOff + 65536u] = pacc[mt][j][1] + pb[j].y;
                    outb[a1 + cOff]          = pacc[mt][j][2] + pb[j].x;
                    outb[a1 + cOff + 65536u] = pacc[mt][j][3] + pb[j].y;
                }
            }
        }
        // no trailing sync: next window's K/V stores are pair-fenced above;
        // A'(saI) reads here are disjoint from SK/SV writes
    }
}

extern "C" void kernel_launch(void* const* d_in, const int* in_sizes, int n_in,
                              void* d_out, int out_size) {
    (void)in_sizes; (void)n_in; (void)out_size;
    const float* x     = (const float*)d_in[0];
    const float* wqkv  = (const float*)d_in[1];
    const float* wproj = (const float*)d_in[2];
    const float* bproj = (const float*)d_in[3];
    float* out = (float*)d_out;

    init_weights_kernel<<<32, 256>>>(wqkv, wproj);

    cudaFuncSetAttribute(swin_mma_kernel,
                         cudaFuncAttributeMaxDynamicSharedMemorySize, SMEM_BYTES);
    swin_mma_kernel<<<GRID, 256, SMEM_BYTES>>>(x, bproj, out);
}

// round 16
// speedup vs baseline: 1.3132x; 1.2285x over previous
#include <cuda_runtime.h>
#include <cuda_fp16.h>
#include <cstdint>

// ---------------- problem constants ----------------
#define SCALE 0.1767766952966369f   // 32^-0.5

// ---------------- smem layout (bytes) ----------------
#define STRC 144                     // A-tile channel-major row stride (bytes)
#define SAW  18464                   // per-window A region
#define STRA 136                     // token-major fp16 row stride (halves) for K/V/A'
#define SK   36928                   // K fp16 tile [64][136]
#define SV   54336                   // V fp16 tile
#define SMEM_BYTES 71744             // 2 CTAs/SM -> ~85 KB L1D left for weights

#define NWIN_PER_CTA 2
#define GRID 4096

// ---------------- ptx helpers ----------------
__device__ __forceinline__ uint32_t smem_u32(const void* p) {
    uint32_t a;
    asm("{ .reg .u64 t; cvta.to.shared.u64 t, %1; cvt.u32.u64 %0, t; }" : "=r"(a) : "l"(p));
    return a;
}
__device__ __forceinline__ void ldsm4(uint32_t* r, uint32_t addr) {
    asm volatile("ldmatrix.sync.aligned.m8n8.x4.shared.b16 {%0,%1,%2,%3}, [%4];"
                 : "=r"(r[0]), "=r"(r[1]), "=r"(r[2]), "=r"(r[3]) : "r"(addr));
}
__device__ __forceinline__ void ldsm4t(uint32_t* r, uint32_t addr) {
    asm volatile("ldmatrix.sync.aligned.m8n8.x4.trans.shared.b16 {%0,%1,%2,%3}, [%4];"
                 : "=r"(r[0]), "=r"(r[1]), "=r"(r[2]), "=r"(r[3]) : "r"(addr));
}
__device__ __forceinline__ void mma16816(float* c, const uint32_t* a,
                                         uint32_t b0, uint32_t b1) {
    asm volatile(
        "mma.sync.aligned.m16n8k16.row.col.f32.f16.f16.f32 "
        "{%0,%1,%2,%3}, {%4,%5,%6,%7}, {%8,%9}, {%0,%1,%2,%3};"
        : "+f"(c[0]), "+f"(c[1]), "+f"(c[2]), "+f"(c[3])
        : "r"(a[0]), "r"(a[1]), "r"(a[2]), "r"(a[3]), "r"(b0), "r"(b1));
}
__device__ __forceinline__ uint32_t pkh2(float x, float y) {
    __half2 H = __halves2half2(__float2half_rn(x), __float2half_rn(y));
    return *(uint32_t*)&H;
}
#define BAR_SYNC(id, cnt) \
    asm volatile("bar.sync %0, %1;" :: "r"(id), "r"(cnt) : "memory")

// ---------------- weight B-fragments in canonical m16n8k16 lane layout ----------
__device__ uint4 g_wfragQKV[3 * 4 * 8 * 2 * 32];   // 96 KB
__device__ uint4 g_wfragP[4 * 8 * 2 * 32];         // 32 KB

__global__ void init_weights_kernel(const float* __restrict__ wqkv,
                                    const float* __restrict__ wproj) {
    int t = blockIdx.x * blockDim.x + threadIdx.x;   // 8192 threads
    bool isP = t >= 6144;
    int e = isP ? t - 6144 : t;
    int lane = e & 31, g = (e >> 5) & 1, kk = (e >> 6) & 7, nbi = (e >> 9) & 3;
    int c = isP ? 0 : (e >> 11);
    int gid = lane >> 2, tig = lane & 3;
    int n_a = nbi * 32 + g * 16 + gid;
    int n_b = n_a + 8;
    int k0 = kk * 16 + 2 * tig;
    float w00, w01, w10, w11, w20, w21, w30, w31;
    if (isP) {
        w00 = wproj[k0 * 128 + n_a];       w01 = wproj[(k0 + 1) * 128 + n_a];
        w10 = wproj[(k0 + 8) * 128 + n_a]; w11 = wproj[(k0 + 9) * 128 + n_a];
        w20 = wproj[k0 * 128 + n_b];       w21 = wproj[(k0 + 1) * 128 + n_b];
        w30 = wproj[(k0 + 8) * 128 + n_b]; w31 = wproj[(k0 + 9) * 128 + n_b];
    } else {
        int nb0 = c * 128;
        w00 = wqkv[k0 * 384 + nb0 + n_a];       w01 = wqkv[(k0 + 1) * 384 + nb0 + n_a];
        w10 = wqkv[(k0 + 8) * 384 + nb0 + n_a]; w11 = wqkv[(k0 + 9) * 384 + nb0 + n_a];
        w20 = wqkv[k0 * 384 + nb0 + n_b];       w21 = wqkv[(k0 + 1) * 384 + nb0 + n_b];
        w30 = wqkv[(k0 + 8) * 384 + nb0 + n_b]; w31 = wqkv[(k0 + 9) * 384 + nb0 + n_b];
    }
    uint4 v;
    v.x = pkh2(w00, w01); v.y = pkh2(w10, w11);
    v.z = pkh2(w20, w21); v.w = pkh2(w30, w31);
    (isP ? g_wfragP : g_wfragQKV)[e] = v;
}

// ---------------- main kernel: 256 threads, 2 CTAs/SM, 2 fused windows/CTA ----
__global__ __launch_bounds__(256, 2)
void swin_mma_kernel(const float* __restrict__ x,
                     const float* __restrict__ bproj,
                     float* __restrict__ out) {
    extern __shared__ char smem[];
    const uint32_t sb = smem_u32(smem);
    const int tid  = threadIdx.x;
    const int wid  = tid >> 5;
    const int lane = tid & 31;

    const int bid  = blockIdx.x;
    const int win0 = bid * NWIN_PER_CTA;
    const int b0   = win0 >> 10;
    const int wh0  = (win0 >> 5) & 31;
    const int ww0  = win0 & 31;

    // warp roles: 2 (M) x 4 (N); warp tile 32 rows x 32 cols
    const int m0  = (wid >> 2) * 32;
    const int nbi = wid & 3;
    const int nb  = nbi * 32;
    const int gid = lane >> 2, tig = lane & 3;

    // named-barrier ids
    const int pairBar = 1 + nbi;
    const int mgBar   = 5 + (wid >> 2);

    // trans-A per-lane offsets (channel-major A tiles)
    const uint32_t kLane = (uint32_t)(((lane & 7) + ((lane >> 4) & 1) * 8) * STRC);
    uint32_t aT[2], aOffP[2];
    #pragma unroll
    for (int mt = 0; mt < 2; ++mt) {
        aT[mt] = kLane + (uint32_t)((m0 + mt * 16 + ((lane >> 3) & 1) * 8) * 2);
        aOffP[mt] = (uint32_t)((m0 + mt * 16 + ((lane >> 3) & 1) * 8 + (lane & 7)) * 272 +
                               (lane >> 4) * 16);
    }
    const uint32_t bRowOff = (uint32_t)((((lane >> 4) & 1) * 8 + (lane & 7)) * 272);
    const uint32_t bKOff   = (uint32_t)(((lane >> 3) & 1) * 16);

    // direct-scatter constants
    int ghA[2][2];
    #pragma unroll
    for (int mt = 0; mt < 2; ++mt) {
        int rr0 = (m0 + mt * 16) >> 3;
        ghA[mt][0] = (wh0 * 8 + rr0 + 4) & 255;
        ghA[mt][1] = (wh0 * 8 + rr0 + 1 + 4) & 255;
    }
    float2 pb[4];
    #pragma unroll
    for (int j = 0; j < 4; ++j) {
        int ccol = nb + j * 8 + 2 * tig;
        pb[j] = make_float2(__ldg(&bproj[ccol]), __ldg(&bproj[ccol + 1]));
    }
    float* outb = out + (size_t)b0 * (128u * 65536u);

    // ---- Prologue: fused 2-window gather, fp32 -> fp16, channel-major A tiles
    {
        const int s0   = ww0 * 8 + 4;
        const int sub  = lane >> 2;            // 0..7: (ch,rr) pair within group
        const int li2  = lane & 3;             // quarter-span within 16-float span
        const int wiA  = li2 >> 1;             // window 0/1
        const int cc8g = (li2 & 1) * 4;
        const int gwb  = (s0 + li2 * 4) & 255;
        const float* xb = x + (size_t)b0 * (128u * 65536u);
        #pragma unroll 4
        for (int it = 0; it < 16; ++it) {
            int pairIdx = wid * 128 + it * 8 + sub;   // 0..1023
            int ch = pairIdx >> 3, rr = pairIdx & 7;
            int gh = (wh0 * 8 + rr + 4) & 255;
            float4 v = __ldg((const float4*)(xb + (size_t)ch * 65536u + gh * 256 + gwb));
            int token = rr * 8 + cc8g;
            uint2 hv;
            hv.x = pkh2(v.x, v.y);
            hv.y = pkh2(v.z, v.w);
            *(uint2*)(smem + wiA * SAW + ch * STRC + token * 2) = hv;
        }
    }
    __syncthreads();

    for (int i = 0; i < NWIN_PER_CTA; ++i) {
        const uint32_t saI = (uint32_t)(i * SAW);
        const int ww = ww0 + i;
        const int gwP = (ww * 8 + gid + 4) & 255;

        // ---- Phase 2a: Q+K GEMM (trans-A from channel-major tile) ----
        uint32_t qf[2][2][4];
        {
            float accA[2][2][4][4];
            #pragma unroll
            for (int c = 0; c < 2; ++c)
                #pragma unroll
                for (int mt = 0; mt < 2; ++mt)
                    #pragma unroll
                    for (int j = 0; j < 4; ++j)
                        #pragma unroll
                        for (int q = 0; q < 4; ++q) accA[c][mt][j][q] = 0.f;

            #pragma unroll
            for (int kk = 0; kk < 8; ++kk) {
                uint32_t ah[2][4];
                ldsm4t(ah[0], sb + saI + aT[0] + kk * (16 * STRC));
                ldsm4t(ah[1], sb + saI + aT[1] + kk * (16 * STRC));
                #pragma unroll
                for (int c = 0; c < 2; ++c) {
                    const int base = (((c * 4 + nbi) * 8 + kk) * 2) * 32 + lane;
                    uint4 w0 = __ldg(&g_wfragQKV[base]);
                    uint4 w1 = __ldg(&g_wfragQKV[base + 32]);
                    uint32_t bb[2][4] = {{w0.x, w0.y, w0.z, w0.w},
                                         {w1.x, w1.y, w1.z, w1.w}};
                    #pragma unroll
                    for (int mt = 0; mt < 2; ++mt)
                        #pragma unroll
                        for (int j = 0; j < 4; ++j) {
                            const int g = j >> 1, e = (j & 1) * 2;
                            mma16816(accA[c][mt][j], ah[mt], bb[g][e], bb[g][e + 1]);
                        }
                }
            }

            #pragma unroll
            for (int mt = 0; mt < 2; ++mt)
                #pragma unroll
                for (int kk2 = 0; kk2 < 2; ++kk2) {
                    qf[mt][kk2][0] = pkh2(accA[0][mt][2 * kk2][0],     accA[0][mt][2 * kk2][1]);
                    qf[mt][kk2][1] = pkh2(accA[0][mt][2 * kk2][2],     accA[0][mt][2 * kk2][3]);
                    qf[mt][kk2][2] = pkh2(accA[0][mt][2 * kk2 + 1][0], accA[0][mt][2 * kk2 + 1][1]);
                    qf[mt][kk2][3] = pkh2(accA[0][mt][2 * kk2 + 1][2], accA[0][mt][2 * kk2 + 1][3]);
                }

            __half* T = (__half*)(smem + SK);
            #pragma unroll
            for (int mt = 0; mt < 2; ++mt)
                #pragma unroll
                for (int j = 0; j < 4; ++j) {
                    int ccol = nb + j * 8 + 2 * tig;
                    *(uint32_t*)&T[(m0 + mt * 16 + gid) * STRA + ccol] =
                        pkh2(accA[1][mt][j][0], accA[1][mt][j][1]);
                    *(uint32_t*)&T[(m0 + mt * 16 + gid + 8) * STRA + ccol] =
                        pkh2(accA[1][mt][j][2], accA[1][mt][j][3]);
                }
        }

        // ---- Phase 2b: V GEMM ----
        {
            float accV[2][4][4];
            #pragma unroll
            for (int mt = 0; mt < 2; ++mt)
                #pragma unroll
                for (int j = 0; j < 4; ++j)
                    #pragma unroll
                    for (int q = 0; q < 4; ++q) accV[mt][j][q] = 0.f;

            #pragma unroll
            for (int kk = 0; kk < 8; ++kk) {
                uint32_t ah[2][4];
                ldsm4t(ah[0], sb + saI + aT[0] + kk * (16 * STRC));
                ldsm4t(ah[1], sb + saI + aT[1] + kk * (16 * STRC));
                const int base = (((2 * 4 + nbi) * 8 + kk) * 2) * 32 + lane;
                uint4 w0 = __ldg(&g_wfragQKV[base]);
                uint4 w1 = __ldg(&g_wfragQKV[base + 32]);
                uint32_t bb[2][4] = {{w0.x, w0.y, w0.z, w0.w}, {w1.x, w1.y, w1.z, w1.w}};
                #pragma unroll
                for (int mt = 0; mt < 2; ++mt)
                    #pragma unroll
                    for (int j = 0; j < 4; ++j) {
                        const int g = j >> 1, e = (j & 1) * 2;
                        mma16816(accV[mt][j], ah[mt], bb[g][e], bb[g][e + 1]);
                    }
            }
            __half* T = (__half*)(smem + SV);
            #pragma unroll
            for (int mt = 0; mt < 2; ++mt)
                #pragma unroll
                for (int j = 0; j < 4; ++j) {
                    int ccol = nb + j * 8 + 2 * tig;
                    *(uint32_t*)&T[(m0 + mt * 16 + gid) * STRA + ccol] =
                        pkh2(accV[mt][j][0], accV[mt][j][1]);
                    *(uint32_t*)&T[(m0 + mt * 16 + gid + 8) * STRA + ccol] =
                        pkh2(accV[mt][j][2], accV[mt][j][3]);
                }
        }
        // CTA-wide: K/V ready AND all channel-major A(i) reads complete
        __syncthreads();

        // ---- Phase 3: attention (1-pass fp16), A' token-major overlays A_i ----
        {
            const int head = nbi;

            float sacc[2][8][4];
            #pragma unroll
            for (int mt = 0; mt < 2; ++mt)
                #pragma unroll
                for (int j = 0; j < 8; ++j)
                    #pragma unroll
                    for (int q = 0; q < 4; ++q) sacc[mt][j][q] = 0.f;

            #pragma unroll
            for (int kk2 = 0; kk2 < 2; ++kk2) {
                const uint32_t ka = kk2 * 32;
                uint32_t kh[4][4];
                #pragma unroll
                for (int g = 0; g < 4; ++g) {
                    uint32_t ro = (uint32_t)(g * 16 * 272) + bRowOff + bKOff +
                                  (uint32_t)(head * 64) + ka;
                    ldsm4(kh[g], sb + SK + ro);
                }
                #pragma unroll
                for (int mt = 0; mt < 2; ++mt)
                    #pragma unroll
                    for (int j = 0; j < 8; ++j) {
                        const int g = j >> 1, e = (j & 1) * 2;
                        mma16816(sacc[mt][j], qf[mt][kk2], kh[g][e], kh[g][e + 1]);
                    }
            }

            const unsigned FULL = 0xffffffffu;
            float inv0[2], inv1[2];
            #pragma unroll
            for (int mt = 0; mt < 2; ++mt) {
                float mx0 = -1e30f, mx1 = -1e30f;
                #pragma unroll
                for (int j = 0; j < 8; ++j) {
                    mx0 = fmaxf(mx0, fmaxf(sacc[mt][j][0], sacc[mt][j][1]));
                    mx1 = fmaxf(mx1, fmaxf(sacc[mt][j][2], sacc[mt][j][3]));
                }
                mx0 = fmaxf(mx0, __shfl_xor_sync(FULL, mx0, 1));
                mx0 = fmaxf(mx0, __shfl_xor_sync(FULL, mx0, 2));
                mx1 = fmaxf(mx1, __shfl_xor_sync(FULL, mx1, 1));
                mx1 = fmaxf(mx1, __shfl_xor_sync(FULL, mx1, 2));
                float sum0 = 0.f, sum1 = 0.f;
                #pragma unroll
                for (int j = 0; j < 8; ++j) {
                    float e0 = __expf((sacc[mt][j][0] - mx0) * SCALE);
                    float e1 = __expf((sacc[mt][j][1] - mx0) * SCALE);
                    float e2 = __expf((sacc[mt][j][2] - mx1) * SCALE);
                    float e3 = __expf((sacc[mt][j][3] - mx1) * SCALE);
                    sacc[mt][j][0] = e0; sacc[mt][j][1] = e1;
                    sacc[mt][j][2] = e2; sacc[mt][j][3] = e3;
                    sum0 += e0 + e1; sum1 += e2 + e3;
                }
                sum0 += __shfl_xor_sync(FULL, sum0, 1);
                sum0 += __shfl_xor_sync(FULL, sum0, 2);
                sum1 += __shfl_xor_sync(FULL, sum1, 1);
                sum1 += __shfl_xor_sync(FULL, sum1, 2);
                inv0[mt] = 1.0f / sum0;
                inv1[mt] = 1.0f / sum1;
            }

            float oacc[2][4][4];
            #pragma unroll
            for (int mt = 0; mt < 2; ++mt)
                #pragma unroll
                for (int j = 0; j < 4; ++j)
                    #pragma unroll
                    for (int q = 0; q < 4; ++q) oacc[mt][j][q] = 0.f;

            const uint32_t vBase =
                (uint32_t)((((lane >> 3) & 1) * 8 + (lane & 7)) * 272 +
                           (head * 32 + (lane >> 4) * 8) * 2);

            #pragma unroll
            for (int t = 0; t < 4; ++t) {
                uint32_t vh[2][4];
                #pragma unroll
                for (int g = 0; g < 2; ++g) {
                    uint32_t ro = vBase + (uint32_t)(t * 16 * 272) + (uint32_t)(g * 32);
                    ldsm4t(vh[g], sb + SV + ro);
                }
                #pragma unroll
                for (int mt = 0; mt < 2; ++mt) {
                    uint32_t ph[4];
                    ph[0] = pkh2(sacc[mt][2 * t][0],     sacc[mt][2 * t][1]);
                    ph[1] = pkh2(sacc[mt][2 * t][2],     sacc[mt][2 * t][3]);
                    ph[2] = pkh2(sacc[mt][2 * t + 1][0], sacc[mt][2 * t + 1][1]);
                    ph[3] = pkh2(sacc[mt][2 * t + 1][2], sacc[mt][2 * t + 1][3]);
                    #pragma unroll
                    for (int j = 0; j < 4; ++j) {
                        const int g = j >> 1, e = (j & 1) * 2;
                        mma16816(oacc[mt][j], ph, vh[g][e], vh[g][e + 1]);
                    }
                }
            }

            // pair barrier: both K/V readers of columns nb done -> safe rewrite
            if (i + 1 < NWIN_PER_CTA) BAR_SYNC(pairBar, 64);

            // normalize + fp16 A' (token-major) overlaying this window's A tile
            __half* Ap = (__half*)(smem + saI);
            #pragma unroll
            for (int mt = 0; mt < 2; ++mt)
                #pragma unroll
                for (int j = 0; j < 4; ++j) {
                    int ccol = head * 32 + j * 8 + 2 * tig;
                    *(uint32_t*)&Ap[(m0 + mt * 16 + gid) * STRA + ccol] =
                        pkh2(oacc[mt][j][0] * inv0[mt], oacc[mt][j][1] * inv0[mt]);
                    *(uint32_t*)&Ap[(m0 + mt * 16 + gid + 8) * STRA + ccol] =
                        pkh2(oacc[mt][j][2] * inv1[mt], oacc[mt][j][3] * inv1[mt]);
                }
        }
        // m-group barrier: A' rows m0..m0+31 visible before proj reads them
        BAR_SYNC(mgBar, 128);

        // ---- Phase 4: proj GEMM + bias, scatter DIRECT from accumulators ----
        {
            float pacc[2][4][4];
            #pragma unroll
            for (int mt = 0; mt < 2; ++mt)
                #pragma unroll
                for (int j = 0; j < 4; ++j)
                    #pragma unroll
                    for (int q = 0; q < 4; ++q) pacc[mt][j][q] = 0.f;

            #pragma unroll
            for (int kk = 0; kk < 8; ++kk) {
                const uint32_t ka = kk * 32;
                uint32_t ah[2][4];
                ldsm4(ah[0], sb + saI + aOffP[0] + ka);
                ldsm4(ah[1], sb + saI + aOffP[1] + ka);
                const int base = ((nbi * 8 + kk) * 2) * 32 + lane;
                uint4 w0 = __ldg(&g_wfragP[base]);
                uint4 w1 = __ldg(&g_wfragP[base + 32]);
                uint32_t bb[2][4] = {{w0.x, w0.y, w0.z, w0.w}, {w1.x, w1.y, w1.z, w1.w}};
                #pragma unroll
                for (int mt = 0; mt < 2; ++mt)
                    #pragma unroll
                    for (int j = 0; j < 4; ++j) {
                        const int g = j >> 1, e = (j & 1) * 2;
                        mma16816(pacc[mt][j], ah[mt], bb[g][e], bb[g][e + 1]);
                    }
            }

            // direct scatter: rows t0 = m0+mt*16+gid (q0,q1), t1 = t0+8 (q2,q3)
            #pragma unroll
            for (int mt = 0; mt < 2; ++mt) {
                const size_t a0 = (size_t)(ghA[mt][0] * 256 + gwP);
                const size_t a1 = (size_t)(ghA[mt][1] * 256 + gwP);
                #pragma unroll
                for (int j = 0; j < 4; ++j) {
                    const size_t cOff = (size_t)(nb + j * 8 + 2 * tig) * 65536u;
                    outb[a0 + cOff]          = pacc[mt][j][0] + pb[j].x;
                    outb[a0 + cOff + 65536u] = pacc[mt][j][1] + pb[j].y;
                    outb[a1 + cOff]          = pacc[mt][j][2] + pb[j].x;
                    outb[a1 + cOff + 65536u] = pacc[mt][j][3] + pb[j].y;
                }
            }
        }
        // no trailing sync: next window's K/V stores pair-fenced above;
        // A'(saI) reads here disjoint from SK/SV writes
    }
}

extern "C" void kernel_launch(void* const* d_in, const int* in_sizes, int n_in,
                              void* d_out, int out_size) {
    (void)in_sizes; (void)n_in; (void)out_size;
    const float* x     = (const float*)d_in[0];
    const float* wqkv  = (const float*)d_in[1];
    const float* wproj = (const float*)d_in[2];
    const float* bproj = (const float*)d_in[3];
    float* out = (float*)d_out;

    init_weights_kernel<<<32, 256>>>(wqkv, wproj);

    cudaFuncSetAttribute(swin_mma_kernel,
                         cudaFuncAttributeMaxDynamicSharedMemorySize, SMEM_BYTES);
    swin_mma_kernel<<<GRID, 256, SMEM_BYTES>>>(x, bproj, out);
}